// round 2
// baseline (speedup 1.0000x reference)
#include <cuda_runtime.h>
#include <cuda_bf16.h>
#include <math_constants.h>

#define BATCH 8
#define NPTS 2500
#define NUM_PATCHES 25
#define PATCH_P 100
#define K_GLOBAL 32
#define K_PATCH 16
#define TOTAL_PTS (BATCH * NPTS)

#define NCHUNK 8
#define CHUNK 313           // ceil(2500/8); last chunk = 309
#define QPB 32              // queries per block

// smem layout (bytes)
#define OFF_SP     0
#define OFF_KEY    40000                       // float4[2500] = 40000
#define OFF_COV    (OFF_KEY + 256*32*4)        // keybuf float[256][32] = 32768
#define OFF_TAU    (OFF_COV + NCHUNK*32*6*4)   // covbuf = 6144
#define SMEM_TOTAL (OFF_TAU + 32*4)            // + tau = 79040

__device__ float g_absn_global[TOTAL_PTS * 3];
__device__ float g_absn_patch[TOTAL_PTS * 3];

// ---------------------------------------------------------------------------
// 3x3 symmetric smallest-eigenvector (double, for robustness), writes |v|.
// ---------------------------------------------------------------------------
__device__ __forceinline__ void smallest_evec_abs(
    float sxx, float sxy, float sxz, float syy, float syz, float szz,
    float out[3])
{
    double a00 = sxx, a01 = sxy, a02 = sxz;
    double a11 = syy, a12 = syz, a22 = szz;

    double p1 = a01 * a01 + a02 * a02 + a12 * a12;
    double q  = (a00 + a11 + a22) * (1.0 / 3.0);
    double d0 = a00 - q, d1 = a11 - q, d2 = a22 - q;
    double p2 = d0 * d0 + d1 * d1 + d2 * d2 + 2.0 * p1;

    double lam;
    if (p2 <= 1e-300) {
        lam = q;
    } else {
        double p   = sqrt(p2 * (1.0 / 6.0));
        double inv = 1.0 / p;
        double b00 = d0 * inv, b11 = d1 * inv, b22 = d2 * inv;
        double b01 = a01 * inv, b02 = a02 * inv, b12 = a12 * inv;
        double detB = b00 * (b11 * b22 - b12 * b12)
                    - b01 * (b01 * b22 - b12 * b02)
                    + b02 * (b01 * b12 - b11 * b02);
        double r = 0.5 * detB;
        r = fmin(1.0, fmax(-1.0, r));
        double phi = acos(r) * (1.0 / 3.0);
        lam = q + 2.0 * p * cos(phi + 2.0943951023931953);
    }

    double r0x = a00 - lam, r0y = a01,       r0z = a02;
    double r1x = a01,       r1y = a11 - lam, r1z = a12;
    double r2x = a02,       r2y = a12,       r2z = a22 - lam;

    double c0x = r0y * r1z - r0z * r1y;
    double c0y = r0z * r1x - r0x * r1z;
    double c0z = r0x * r1y - r0y * r1x;

    double c1x = r0y * r2z - r0z * r2y;
    double c1y = r0z * r2x - r0x * r2z;
    double c1z = r0x * r2y - r0y * r2x;

    double c2x = r1y * r2z - r1z * r2y;
    double c2y = r1z * r2x - r1x * r2z;
    double c2z = r1x * r2y - r1y * r2x;

    double n0 = c0x * c0x + c0y * c0y + c0z * c0z;
    double n1 = c1x * c1x + c1y * c1y + c1z * c1z;
    double n2 = c2x * c2x + c2y * c2y + c2z * c2z;

    double vx = c0x, vy = c0y, vz = c0z, nn = n0;
    if (n1 > nn) { vx = c1x; vy = c1y; vz = c1z; nn = n1; }
    if (n2 > nn) { vx = c2x; vy = c2y; vz = c2z; nn = n2; }
    if (nn < 1e-300) { vx = 1.0; vy = 0.0; vz = 0.0; nn = 1.0; }

    double invn = rsqrt(nn);
    out[0] = (float)fabs(vx * invn);
    out[1] = (float)fabs(vy * invn);
    out[2] = (float)fabs(vz * invn);
}

// Values-only top-K tracker (replace-max).
template <int K>
__device__ __forceinline__ void insertK(float (&h)[K], float &hmax, float key)
{
    bool done = false;
#pragma unroll
    for (int t = 0; t < K; ++t) {
        if (!done && h[t] == hmax) { h[t] = key; done = true; }
    }
    float m = h[0];
#pragma unroll
    for (int t = 1; t < K; ++t) m = fmaxf(m, h[t]);
    hmax = m;
}

// ---------------------------------------------------------------------------
// Global 32-NN normals. grid = (79, 8), block = 256 = 32 queries x 8 chunks.
// Phase 1: per-chunk top-32 key values. Phase 2: exact 32nd key (tau).
// Phase 3: rescan chunk, accumulate cov for key <= tau. Phase 4: eigen.
// ---------------------------------------------------------------------------
__global__ void __launch_bounds__(256)
knn_global_kernel(const float* __restrict__ pc)
{
    extern __shared__ char smem_raw[];
    float4* sp     = (float4*)(smem_raw + OFF_SP);
    float*  keybuf = (float*)(smem_raw + OFF_KEY);   // [256][32]
    float*  covbuf = (float*)(smem_raw + OFF_COV);   // [8*32][6]
    float*  tauv   = (float*)(smem_raw + OFF_TAU);   // [32]

    const int tid = threadIdx.x;
    const int b = blockIdx.y;
    const float* base = pc + (size_t)b * NPTS * 3;

    for (int j = tid; j < NPTS; j += 256) {
        float x = base[3 * j + 0];
        float y = base[3 * j + 1];
        float z = base[3 * j + 2];
        sp[j] = make_float4(x, y, z, fmaf(x, x, fmaf(y, y, z * z)));
    }
    __syncthreads();

    const int ql = tid & 31;          // local query 0..31
    const int c  = tid >> 5;          // chunk 0..7
    const int qg = blockIdx.x * QPB + ql;
    const int qi = (qg < NPTS) ? qg : (NPTS - 1);

    const float4 qv = sp[qi];
    const float qx = qv.x, qy = qv.y, qz = qv.z;

    const int j0 = c * CHUNK;
    const int j1 = (j0 + CHUNK < NPTS) ? (j0 + CHUNK) : NPTS;

    // Phase 1: chunk top-32 (values only)
    {
        float heap[K_GLOBAL];
#pragma unroll
        for (int t = 0; t < K_GLOBAL; ++t) heap[t] = CUDART_INF_F;
        float hmax = CUDART_INF_F;

        for (int j = j0; j < j1; ++j) {
            float4 p = sp[j];
            float dot = fmaf(qx, p.x, fmaf(qy, p.y, qz * p.z));
            float key = fmaf(-2.0f, dot, p.w);
            if (key < hmax) insertK<K_GLOBAL>(heap, hmax, key);
        }
#pragma unroll
        for (int t = 0; t < K_GLOBAL; ++t)
            keybuf[(c * K_GLOBAL + t) * 32 + ql] = heap[t];
    }
    __syncthreads();

    // Phase 2: exact 32nd smallest over union of 256 keys.
    // Merge thread for query q = tid>>3 runs on lanes 0,8,16,24 of each warp.
    if ((tid & 7) == 0) {
        const int q = tid >> 3;
        float heap[K_GLOBAL];
#pragma unroll
        for (int t = 0; t < K_GLOBAL; ++t) heap[t] = CUDART_INF_F;
        float hmax = CUDART_INF_F;
#pragma unroll 4
        for (int j = 0; j < NCHUNK * K_GLOBAL; ++j) {
            float key = keybuf[j * 32 + q];
            if (key < hmax) insertK<K_GLOBAL>(heap, hmax, key);
        }
        tauv[q] = hmax;
    }
    __syncthreads();

    // Phase 3: rescan own chunk, accumulate cov where key <= tau
    {
        const float tq = tauv[ql];
        float xx = 0.f, xy = 0.f, xz = 0.f, yy = 0.f, yz = 0.f, zz = 0.f;
        for (int j = j0; j < j1; ++j) {
            float4 p = sp[j];
            float dot = fmaf(qx, p.x, fmaf(qy, p.y, qz * p.z));
            float key = fmaf(-2.0f, dot, p.w);
            if (key <= tq) {
                float dx = p.x - qx, dy = p.y - qy, dz = p.z - qz;
                xx = fmaf(dx, dx, xx);
                xy = fmaf(dx, dy, xy);
                xz = fmaf(dx, dz, xz);
                yy = fmaf(dy, dy, yy);
                yz = fmaf(dy, dz, yz);
                zz = fmaf(dz, dz, zz);
            }
        }
        float* cb = covbuf + (c * 32 + ql) * 6;
        cb[0] = xx; cb[1] = xy; cb[2] = xz; cb[3] = yy; cb[4] = yz; cb[5] = zz;
    }
    __syncthreads();

    // Phase 4: reduce partial covs + eigen (warp 0)
    if (tid < 32) {
        const int q = tid;
        float s[6] = {0.f, 0.f, 0.f, 0.f, 0.f, 0.f};
#pragma unroll
        for (int cc = 0; cc < NCHUNK; ++cc) {
            const float* cb = covbuf + (cc * 32 + q) * 6;
#pragma unroll
            for (int k = 0; k < 6; ++k) s[k] += cb[k];
        }
        const int qout = blockIdx.x * QPB + q;
        if (qout < NPTS) {
            float out[3];
            smallest_evec_abs(s[0], s[1], s[2], s[3], s[4], s[5], out);
            const int g = (b * NPTS + qout) * 3;
            g_absn_global[g + 0] = out[0];
            g_absn_global[g + 1] = out[1];
            g_absn_global[g + 2] = out[2];
        }
    }
}

// ---------------------------------------------------------------------------
// Patch 16-NN normals: 200 blocks x 128 threads, per-thread full scan (cheap).
// ---------------------------------------------------------------------------
__global__ void __launch_bounds__(128)
knn_patch_kernel(const float* __restrict__ pc)
{
    __shared__ float4 sp[PATCH_P];

    const int p = blockIdx.x;
    const float* base = pc + (size_t)p * PATCH_P * 3;

    for (int j = threadIdx.x; j < PATCH_P; j += 128) {
        float x = base[3 * j + 0];
        float y = base[3 * j + 1];
        float z = base[3 * j + 2];
        sp[j] = make_float4(x, y, z, fmaf(x, x, fmaf(y, y, z * z)));
    }
    __syncthreads();

    const int l = threadIdx.x;
    if (l < PATCH_P) {
        const float4 qv = sp[l];
        const float qx = qv.x, qy = qv.y, qz = qv.z;

        float heap[K_PATCH];
#pragma unroll
        for (int t = 0; t < K_PATCH; ++t) heap[t] = CUDART_INF_F;
        float hmax = CUDART_INF_F;

        for (int j = 0; j < PATCH_P; ++j) {
            float4 c = sp[j];
            float dot = fmaf(qx, c.x, fmaf(qy, c.y, qz * c.z));
            float key = fmaf(-2.0f, dot, c.w);
            if (key < hmax) insertK<K_PATCH>(heap, hmax, key);
        }

        // rescan with tau = hmax (exact top-16 set)
        float xx = 0.f, xy = 0.f, xz = 0.f, yy = 0.f, yz = 0.f, zz = 0.f;
        for (int j = 0; j < PATCH_P; ++j) {
            float4 c = sp[j];
            float dot = fmaf(qx, c.x, fmaf(qy, c.y, qz * c.z));
            float key = fmaf(-2.0f, dot, c.w);
            if (key <= hmax) {
                float dx = c.x - qx, dy = c.y - qy, dz = c.z - qz;
                xx = fmaf(dx, dx, xx);
                xy = fmaf(dx, dy, xy);
                xz = fmaf(dx, dz, xz);
                yy = fmaf(dy, dy, yy);
                yz = fmaf(dy, dz, yz);
                zz = fmaf(dz, dz, zz);
            }
        }

        float out[3];
        smallest_evec_abs(xx, xy, xz, yy, yz, zz, out);
        const int g = (p * PATCH_P + l) * 3;
        g_absn_patch[g + 0] = out[0];
        g_absn_patch[g + 1] = out[1];
        g_absn_patch[g + 2] = out[2];
    }
}

// ---------------------------------------------------------------------------
__global__ void zero_out_kernel(float* out) { out[0] = 0.0f; }

__global__ void __launch_bounds__(256)
loss_kernel(float* __restrict__ out)
{
    const int i = blockIdx.x * 256 + threadIdx.x;
    float v = 0.0f;
    if (i < TOTAL_PTS) {
        const int g = 3 * i;
        float dx = g_absn_patch[g + 0] - g_absn_global[g + 0];
        float dy = g_absn_patch[g + 1] - g_absn_global[g + 1];
        float dz = g_absn_patch[g + 2] - g_absn_global[g + 2];
        v = sqrtf(fmaf(dx, dx, fmaf(dy, dy, dz * dz)));
    }
#pragma unroll
    for (int off = 16; off > 0; off >>= 1)
        v += __shfl_down_sync(0xFFFFFFFFu, v, off);

    __shared__ float warpsum[8];
    const int lane = threadIdx.x & 31;
    const int wid  = threadIdx.x >> 5;
    if (lane == 0) warpsum[wid] = v;
    __syncthreads();

    if (wid == 0) {
        float s = (lane < 8) ? warpsum[lane] : 0.0f;
#pragma unroll
        for (int off = 4; off > 0; off >>= 1)
            s += __shfl_down_sync(0xFFFFFFFFu, s, off);
        if (lane == 0)
            atomicAdd(out, s * (1.0f / (float)TOTAL_PTS));
    }
}

// ---------------------------------------------------------------------------
extern "C" void kernel_launch(void* const* d_in, const int* in_sizes, int n_in,
                              void* d_out, int out_size)
{
    const float* pc = (const float*)d_in[0];
    float* out = (float*)d_out;

    cudaFuncSetAttribute(knn_global_kernel,
                         cudaFuncAttributeMaxDynamicSharedMemorySize,
                         SMEM_TOTAL);

    zero_out_kernel<<<1, 1>>>(out);

    dim3 gGrid((NPTS + QPB - 1) / QPB, BATCH);   // (79, 8)
    knn_global_kernel<<<gGrid, 256, SMEM_TOTAL>>>(pc);

    knn_patch_kernel<<<BATCH * NUM_PATCHES, 128>>>(pc);

    loss_kernel<<<(TOTAL_PTS + 255) / 256, 256>>>(out);
}

// round 3
// speedup vs baseline: 27.4380x; 27.4380x over previous
#include <cuda_runtime.h>
#include <cuda_bf16.h>
#include <math_constants.h>

#define BATCH 8
#define NPTS 2500
#define NUM_PATCHES 25
#define PATCH_P 100
#define K_GLOBAL 32
#define K_PATCH 16
#define TOTAL_PTS (BATCH * NPTS)

#define WARPS_PER_BLOCK 16           // 512 threads, 16 queries/block
#define NSTEP 79                     // ceil(2500/32)

__device__ float g_cov_global[TOTAL_PTS * 6];
__device__ float g_cov_patch[TOTAL_PTS * 6];

// ---------------------------------------------------------------------------
// 3x3 symmetric smallest-eigenvector (double), writes |v|.
// ---------------------------------------------------------------------------
__device__ __forceinline__ void smallest_evec_abs(
    const float* s, float out[3])
{
    double a00 = s[0], a01 = s[1], a02 = s[2];
    double a11 = s[3], a12 = s[4], a22 = s[5];

    double p1 = a01 * a01 + a02 * a02 + a12 * a12;
    double q  = (a00 + a11 + a22) * (1.0 / 3.0);
    double d0 = a00 - q, d1 = a11 - q, d2 = a22 - q;
    double p2 = d0 * d0 + d1 * d1 + d2 * d2 + 2.0 * p1;

    double lam;
    if (p2 <= 1e-300) {
        lam = q;
    } else {
        double p   = sqrt(p2 * (1.0 / 6.0));
        double inv = 1.0 / p;
        double b00 = d0 * inv, b11 = d1 * inv, b22 = d2 * inv;
        double b01 = a01 * inv, b02 = a02 * inv, b12 = a12 * inv;
        double detB = b00 * (b11 * b22 - b12 * b12)
                    - b01 * (b01 * b22 - b12 * b02)
                    + b02 * (b01 * b12 - b11 * b02);
        double r = 0.5 * detB;
        r = fmin(1.0, fmax(-1.0, r));
        double phi = acos(r) * (1.0 / 3.0);
        lam = q + 2.0 * p * cos(phi + 2.0943951023931953);
    }

    double r0x = a00 - lam, r0y = a01,       r0z = a02;
    double r1x = a01,       r1y = a11 - lam, r1z = a12;
    double r2x = a02,       r2y = a12,       r2z = a22 - lam;

    double c0x = r0y * r1z - r0z * r1y;
    double c0y = r0z * r1x - r0x * r1z;
    double c0z = r0x * r1y - r0y * r1x;

    double c1x = r0y * r2z - r0z * r2y;
    double c1y = r0z * r2x - r0x * r2z;
    double c1z = r0x * r2y - r0y * r2x;

    double c2x = r1y * r2z - r1z * r2y;
    double c2y = r1z * r2x - r1x * r2z;
    double c2z = r1x * r2y - r1y * r2x;

    double n0 = c0x * c0x + c0y * c0y + c0z * c0z;
    double n1 = c1x * c1x + c1y * c1y + c1z * c1z;
    double n2 = c2x * c2x + c2y * c2y + c2z * c2z;

    double vx = c0x, vy = c0y, vz = c0z, nn = n0;
    if (n1 > nn) { vx = c1x; vy = c1y; vz = c1z; nn = n1; }
    if (n2 > nn) { vx = c2x; vy = c2y; vz = c2z; nn = n2; }
    if (nn < 1e-300) { vx = 1.0; vy = 0.0; vz = 0.0; nn = 1.0; }

    double invn = rsqrt(nn);
    out[0] = (float)fabs(vx * invn);
    out[1] = (float)fabs(vy * invn);
    out[2] = (float)fabs(vz * invn);
}

// ---------------------------------------------------------------------------
// Global 32-NN: one warp per query, warp-distributed bitonic top-32.
// The running top-32 is one value per lane, sorted ascending by lane id.
// ---------------------------------------------------------------------------
__global__ void __launch_bounds__(512)
knn_global_kernel(const float* __restrict__ pc)
{
    __shared__ float4 sp[NPTS];   // 40 KB (static, <48KB)

    const int b = blockIdx.y;
    const float* base = pc + (size_t)b * NPTS * 3;

    for (int j = threadIdx.x; j < NPTS; j += 512) {
        float x = base[3 * j + 0];
        float y = base[3 * j + 1];
        float z = base[3 * j + 2];
        sp[j] = make_float4(x, y, z, fmaf(x, x, fmaf(y, y, z * z)));
    }
    __syncthreads();

    const int warp = threadIdx.x >> 5;
    const int lane = threadIdx.x & 31;
    const int q = blockIdx.x * WARPS_PER_BLOCK + warp;
    if (q >= NPTS) return;

    const unsigned FULL = 0xFFFFFFFFu;
    const float4 qv = sp[q];
    const float qx = qv.x, qy = qv.y, qz = qv.z;

    float v = CUDART_INF_F;   // lane's slot of the sorted top-32

    for (int n = 0; n < NSTEP; ++n) {
        const int j = n * 32 + lane;
        float key = CUDART_INF_F;
        if (j < NPTS) {
            float4 p = sp[j];
            float dot = fmaf(qx, p.x, fmaf(qy, p.y, qz * p.z));
            key = fmaf(-2.0f, dot, p.w);
        }

        const float tau = __shfl_sync(FULL, v, 31);
        if (__ballot_sync(FULL, key < tau)) {
            // bitonic sort the 32 new keys ascending across lanes
#pragma unroll
            for (int size = 2; size <= 32; size <<= 1) {
#pragma unroll
                for (int stride = size >> 1; stride > 0; stride >>= 1) {
                    float other = __shfl_xor_sync(FULL, key, stride);
                    bool takeMin = ((lane & size) == 0) == ((lane & stride) == 0);
                    key = takeMin ? fminf(key, other) : fmaxf(key, other);
                }
            }
            // half-cleaner: keep lowest 32 of union (bitonic partner = reversed)
            float r = __shfl_sync(FULL, key, 31 - lane);
            v = fminf(v, r);
            // clean bitonic sequence -> ascending sorted
#pragma unroll
            for (int stride = 16; stride > 0; stride >>= 1) {
                float other = __shfl_xor_sync(FULL, v, stride);
                bool takeMin = (lane & stride) == 0;
                v = takeMin ? fminf(v, other) : fmaxf(v, other);
            }
        }
    }

    const float tau = __shfl_sync(FULL, v, 31);   // exact 32nd-smallest key

    // rescan: accumulate covariance of query-centered points with key <= tau
    float xx = 0.f, xy = 0.f, xz = 0.f, yy = 0.f, yz = 0.f, zz = 0.f;
    for (int n = 0; n < NSTEP; ++n) {
        const int j = n * 32 + lane;
        if (j < NPTS) {
            float4 p = sp[j];
            float dot = fmaf(qx, p.x, fmaf(qy, p.y, qz * p.z));
            float key = fmaf(-2.0f, dot, p.w);
            if (key <= tau) {
                float dx = p.x - qx, dy = p.y - qy, dz = p.z - qz;
                xx = fmaf(dx, dx, xx);
                xy = fmaf(dx, dy, xy);
                xz = fmaf(dx, dz, xz);
                yy = fmaf(dy, dy, yy);
                yz = fmaf(dy, dz, yz);
                zz = fmaf(dz, dz, zz);
            }
        }
    }

#pragma unroll
    for (int off = 16; off > 0; off >>= 1) {
        xx += __shfl_xor_sync(FULL, xx, off);
        xy += __shfl_xor_sync(FULL, xy, off);
        xz += __shfl_xor_sync(FULL, xz, off);
        yy += __shfl_xor_sync(FULL, yy, off);
        yz += __shfl_xor_sync(FULL, yz, off);
        zz += __shfl_xor_sync(FULL, zz, off);
    }

    if (lane == 0) {
        float* cb = g_cov_global + (size_t)(b * NPTS + q) * 6;
        cb[0] = xx; cb[1] = xy; cb[2] = xz; cb[3] = yy; cb[4] = yz; cb[5] = zz;
    }
}

// ---------------------------------------------------------------------------
// Patch 16-NN: per-thread heap over only 100 candidates (cheap), cov out.
// ---------------------------------------------------------------------------
__global__ void __launch_bounds__(128)
knn_patch_kernel(const float* __restrict__ pc)
{
    __shared__ float4 sp[PATCH_P];

    const int p = blockIdx.x;
    const float* base = pc + (size_t)p * PATCH_P * 3;

    for (int j = threadIdx.x; j < PATCH_P; j += 128) {
        float x = base[3 * j + 0];
        float y = base[3 * j + 1];
        float z = base[3 * j + 2];
        sp[j] = make_float4(x, y, z, fmaf(x, x, fmaf(y, y, z * z)));
    }
    __syncthreads();

    const int l = threadIdx.x;
    if (l < PATCH_P) {
        const float4 qv = sp[l];
        const float qx = qv.x, qy = qv.y, qz = qv.z;

        float heap[K_PATCH];
#pragma unroll
        for (int t = 0; t < K_PATCH; ++t) heap[t] = CUDART_INF_F;
        float hmax = CUDART_INF_F;

        for (int j = 0; j < PATCH_P; ++j) {
            float4 c = sp[j];
            float dot = fmaf(qx, c.x, fmaf(qy, c.y, qz * c.z));
            float key = fmaf(-2.0f, dot, c.w);
            if (key < hmax) {
                bool done = false;
#pragma unroll
                for (int t = 0; t < K_PATCH; ++t) {
                    if (!done && heap[t] == hmax) { heap[t] = key; done = true; }
                }
                float m = heap[0];
#pragma unroll
                for (int t = 1; t < K_PATCH; ++t) m = fmaxf(m, heap[t]);
                hmax = m;
            }
        }

        float xx = 0.f, xy = 0.f, xz = 0.f, yy = 0.f, yz = 0.f, zz = 0.f;
        for (int j = 0; j < PATCH_P; ++j) {
            float4 c = sp[j];
            float dot = fmaf(qx, c.x, fmaf(qy, c.y, qz * c.z));
            float key = fmaf(-2.0f, dot, c.w);
            if (key <= hmax) {
                float dx = c.x - qx, dy = c.y - qy, dz = c.z - qz;
                xx = fmaf(dx, dx, xx);
                xy = fmaf(dx, dy, xy);
                xz = fmaf(dx, dz, xz);
                yy = fmaf(dy, dy, yy);
                yz = fmaf(dy, dz, yz);
                zz = fmaf(dz, dz, zz);
            }
        }

        float* cb = g_cov_patch + (size_t)(p * PATCH_P + l) * 6;
        cb[0] = xx; cb[1] = xy; cb[2] = xz; cb[3] = yy; cb[4] = yz; cb[5] = zz;
    }
}

// ---------------------------------------------------------------------------
// Loss: per point, eigen(cov_patch) & eigen(cov_global), norm of abs-diff.
// ---------------------------------------------------------------------------
__global__ void zero_out_kernel(float* out) { out[0] = 0.0f; }

__global__ void __launch_bounds__(256)
loss_kernel(float* __restrict__ out)
{
    const int i = blockIdx.x * 256 + threadIdx.x;
    float v = 0.0f;
    if (i < TOTAL_PTS) {
        float ng[3], np_[3];
        smallest_evec_abs(g_cov_global + (size_t)i * 6, ng);
        smallest_evec_abs(g_cov_patch  + (size_t)i * 6, np_);
        float dx = np_[0] - ng[0];
        float dy = np_[1] - ng[1];
        float dz = np_[2] - ng[2];
        v = sqrtf(fmaf(dx, dx, fmaf(dy, dy, dz * dz)));
    }
#pragma unroll
    for (int off = 16; off > 0; off >>= 1)
        v += __shfl_down_sync(0xFFFFFFFFu, v, off);

    __shared__ float warpsum[8];
    const int lane = threadIdx.x & 31;
    const int wid  = threadIdx.x >> 5;
    if (lane == 0) warpsum[wid] = v;
    __syncthreads();

    if (wid == 0) {
        float s = (lane < 8) ? warpsum[lane] : 0.0f;
#pragma unroll
        for (int off = 4; off > 0; off >>= 1)
            s += __shfl_down_sync(0xFFFFFFFFu, s, off);
        if (lane == 0)
            atomicAdd(out, s * (1.0f / (float)TOTAL_PTS));
    }
}

// ---------------------------------------------------------------------------
extern "C" void kernel_launch(void* const* d_in, const int* in_sizes, int n_in,
                              void* d_out, int out_size)
{
    const float* pc = (const float*)d_in[0];
    float* out = (float*)d_out;

    zero_out_kernel<<<1, 1>>>(out);

    dim3 gGrid((NPTS + WARPS_PER_BLOCK - 1) / WARPS_PER_BLOCK, BATCH); // (157, 8)
    knn_global_kernel<<<gGrid, 512>>>(pc);

    knn_patch_kernel<<<BATCH * NUM_PATCHES, 128>>>(pc);

    loss_kernel<<<(TOTAL_PTS + 255) / 256, 256>>>(out);
}

// round 4
// speedup vs baseline: 48.4667x; 1.7664x over previous
#include <cuda_runtime.h>
#include <cuda_bf16.h>
#include <math_constants.h>
#include <cfloat>

#define BATCH 8
#define NPTS 2500
#define NUM_PATCHES 25
#define PATCH_P 100
#define TOTAL_PTS (BATCH * NPTS)        // 20000
#define TOTAL_PATCHES (BATCH * NUM_PATCHES)  // 200

#define WPB 16                 // warps (=queries) per block
#define NSTEP_G 79             // ceil(2500/32)
#define NPAD_G (NSTEP_G * 32)  // 2528
#define NSTEP_P 4              // ceil(100/32) padded to 128

__device__ float g_cov_global[TOTAL_PTS * 6];
__device__ float g_cov_patch[TOTAL_PTS * 6];

// ---------------------------------------------------------------------------
// 3x3 symmetric smallest-eigenvector (double), writes |v|.
// ---------------------------------------------------------------------------
__device__ __forceinline__ void smallest_evec_abs(
    const float* s, float out[3])
{
    double a00 = s[0], a01 = s[1], a02 = s[2];
    double a11 = s[3], a12 = s[4], a22 = s[5];

    double p1 = a01 * a01 + a02 * a02 + a12 * a12;
    double q  = (a00 + a11 + a22) * (1.0 / 3.0);
    double d0 = a00 - q, d1 = a11 - q, d2 = a22 - q;
    double p2 = d0 * d0 + d1 * d1 + d2 * d2 + 2.0 * p1;

    double lam;
    if (p2 <= 1e-300) {
        lam = q;
    } else {
        double p   = sqrt(p2 * (1.0 / 6.0));
        double inv = 1.0 / p;
        double b00 = d0 * inv, b11 = d1 * inv, b22 = d2 * inv;
        double b01 = a01 * inv, b02 = a02 * inv, b12 = a12 * inv;
        double detB = b00 * (b11 * b22 - b12 * b12)
                    - b01 * (b01 * b22 - b12 * b02)
                    + b02 * (b01 * b12 - b11 * b02);
        double r = 0.5 * detB;
        r = fmin(1.0, fmax(-1.0, r));
        double phi = acos(r) * (1.0 / 3.0);
        lam = q + 2.0 * p * cos(phi + 2.0943951023931953);
    }

    double r0x = a00 - lam, r0y = a01,       r0z = a02;
    double r1x = a01,       r1y = a11 - lam, r1z = a12;
    double r2x = a02,       r2y = a12,       r2z = a22 - lam;

    double c0x = r0y * r1z - r0z * r1y;
    double c0y = r0z * r1x - r0x * r1z;
    double c0z = r0x * r1y - r0y * r1x;

    double c1x = r0y * r2z - r0z * r2y;
    double c1y = r0z * r2x - r0x * r2z;
    double c1z = r0x * r2y - r0y * r2x;

    double c2x = r1y * r2z - r1z * r2y;
    double c2y = r1z * r2x - r1x * r2z;
    double c2z = r1x * r2y - r1y * r2x;

    double n0 = c0x * c0x + c0y * c0y + c0z * c0z;
    double n1 = c1x * c1x + c1y * c1y + c1z * c1z;
    double n2 = c2x * c2x + c2y * c2y + c2z * c2z;

    double vx = c0x, vy = c0y, vz = c0z, nn = n0;
    if (n1 > nn) { vx = c1x; vy = c1y; vz = c1z; nn = n1; }
    if (n2 > nn) { vx = c2x; vy = c2y; vz = c2z; nn = n2; }
    if (nn < 1e-300) { vx = 1.0; vy = 0.0; vz = 0.0; nn = 1.0; }

    double invn = rsqrt(nn);
    out[0] = (float)fabs(vx * invn);
    out[1] = (float)fabs(vy * invn);
    out[2] = (float)fabs(vz * invn);
}

// ---------------------------------------------------------------------------
// Warp-distributed exact k-th smallest key. Maintains the 32 smallest keys
// seen so far, sorted ascending across lanes. Cheap scalar insertion when
// few candidates pass; full bitonic merge otherwise. Returns tau broadcast.
// sp must be padded to nstep*32 entries with w = FLT_MAX sentinels.
// ---------------------------------------------------------------------------
__device__ __forceinline__ float warp_topk_tau(
    const float4* __restrict__ sp, int nstep,
    float qx, float qy, float qz, int lane, int tauLane)
{
    const unsigned FULL = 0xFFFFFFFFu;
    float v   = CUDART_INF_F;
    float tau = CUDART_INF_F;

    for (int n = 0; n < nstep; ++n) {
        float4 p = sp[n * 32 + lane];
        float dot = fmaf(qx, p.x, fmaf(qy, p.y, qz * p.z));
        float key = fmaf(-2.0f, dot, p.w);

        unsigned mask = __ballot_sync(FULL, key < tau);
        if (mask) {
            if (__popc(mask) <= 5) {
                // scalar insertions into the sorted array
                do {
                    int src = __ffs(mask) - 1;
                    mask &= mask - 1;
                    float k  = __shfl_sync(FULL, key, src);
                    float vp = __shfl_up_sync(FULL, v, 1);
                    if (lane == 0) vp = -CUDART_INF_F;
                    v = (v < k) ? v : ((vp < k) ? k : vp);
                } while (mask);
            } else {
                // bitonic sort the 32 candidate keys ascending
#pragma unroll
                for (int size = 2; size <= 32; size <<= 1) {
#pragma unroll
                    for (int stride = size >> 1; stride > 0; stride >>= 1) {
                        float o = __shfl_xor_sync(FULL, key, stride);
                        bool mn = ((lane & size) == 0) == ((lane & stride) == 0);
                        key = mn ? fminf(key, o) : fmaxf(key, o);
                    }
                }
                // keep lowest 32 of union, then clean to ascending
                float r = __shfl_sync(FULL, key, 31 - lane);
                v = fminf(v, r);
#pragma unroll
                for (int stride = 16; stride > 0; stride >>= 1) {
                    float o = __shfl_xor_sync(FULL, v, stride);
                    v = ((lane & stride) == 0) ? fminf(v, o) : fmaxf(v, o);
                }
            }
            tau = __shfl_sync(FULL, v, tauLane);
        }
    }
    return tau;
}

// Rescan: covariance of query-centered points with key <= tau; lane0 stores.
__device__ __forceinline__ void warp_cov_store(
    const float4* __restrict__ sp, int nstep,
    float qx, float qy, float qz, int lane, float tau, float* __restrict__ cb)
{
    const unsigned FULL = 0xFFFFFFFFu;
    float xx = 0.f, xy = 0.f, xz = 0.f, yy = 0.f, yz = 0.f, zz = 0.f;
    for (int n = 0; n < nstep; ++n) {
        float4 p = sp[n * 32 + lane];
        float dot = fmaf(qx, p.x, fmaf(qy, p.y, qz * p.z));
        float key = fmaf(-2.0f, dot, p.w);
        if (key <= tau) {
            float dx = p.x - qx, dy = p.y - qy, dz = p.z - qz;
            xx = fmaf(dx, dx, xx);
            xy = fmaf(dx, dy, xy);
            xz = fmaf(dx, dz, xz);
            yy = fmaf(dy, dy, yy);
            yz = fmaf(dy, dz, yz);
            zz = fmaf(dz, dz, zz);
        }
    }
#pragma unroll
    for (int off = 16; off > 0; off >>= 1) {
        xx += __shfl_xor_sync(FULL, xx, off);
        xy += __shfl_xor_sync(FULL, xy, off);
        xz += __shfl_xor_sync(FULL, xz, off);
        yy += __shfl_xor_sync(FULL, yy, off);
        yz += __shfl_xor_sync(FULL, yz, off);
        zz += __shfl_xor_sync(FULL, zz, off);
    }
    if (lane == 0) {
        cb[0] = xx; cb[1] = xy; cb[2] = xz;
        cb[3] = yy; cb[4] = yz; cb[5] = zz;
    }
}

// ---------------------------------------------------------------------------
// Global 32-NN: one warp per query.
// ---------------------------------------------------------------------------
__global__ void __launch_bounds__(512, 3)
knn_global_kernel(const float* __restrict__ pc)
{
    __shared__ float4 sp[NPAD_G];   // 40448 B, sentinel-padded

    const int b = blockIdx.y;
    const float* base = pc + (size_t)b * NPTS * 3;

    for (int j = threadIdx.x; j < NPAD_G; j += 512) {
        float4 val = make_float4(0.f, 0.f, 0.f, FLT_MAX);
        if (j < NPTS) {
            float x = base[3 * j + 0];
            float y = base[3 * j + 1];
            float z = base[3 * j + 2];
            val = make_float4(x, y, z, fmaf(x, x, fmaf(y, y, z * z)));
        }
        sp[j] = val;
    }
    __syncthreads();

    const int warp = threadIdx.x >> 5;
    const int lane = threadIdx.x & 31;
    const int q = blockIdx.x * WPB + warp;
    if (q >= NPTS) return;

    const float4 qv = sp[q];
    float tau = warp_topk_tau(sp, NSTEP_G, qv.x, qv.y, qv.z, lane, 31);
    warp_cov_store(sp, NSTEP_G, qv.x, qv.y, qv.z, lane, tau,
                   g_cov_global + (size_t)(b * NPTS + q) * 6);
}

// ---------------------------------------------------------------------------
// Patch 16-NN: one warp per query; block covers 16 queries (<= 2 patches).
// grid.x = 20000/16 = 1250.
// ---------------------------------------------------------------------------
__global__ void __launch_bounds__(512, 3)
knn_patch_kernel(const float* __restrict__ pc)
{
    __shared__ float4 spp[2 * 128];   // two patches, padded to 128 each

    const int q0 = blockIdx.x * WPB;      // first global query id
    const int p0 = q0 / PATCH_P;          // first patch id

    for (int t = threadIdx.x; t < 256; t += 512) {
        const int which = t >> 7;         // 0 or 1
        const int local = t & 127;
        const int pp = p0 + which;
        float4 val = make_float4(0.f, 0.f, 0.f, FLT_MAX);
        if (local < PATCH_P && pp < TOTAL_PATCHES) {
            const float* bb = pc + (size_t)pp * PATCH_P * 3;
            float x = bb[3 * local + 0];
            float y = bb[3 * local + 1];
            float z = bb[3 * local + 2];
            val = make_float4(x, y, z, fmaf(x, x, fmaf(y, y, z * z)));
        }
        spp[(which << 7) + local] = val;
    }
    __syncthreads();

    const int warp = threadIdx.x >> 5;
    const int lane = threadIdx.x & 31;
    const int gq = q0 + warp;             // < 20000 always (1250*16 = 20000)
    const int pp = gq / PATCH_P;
    const int ql = gq % PATCH_P;
    const float4* sp = spp + ((pp - p0) << 7);

    const float4 qv = sp[ql];
    float tau = warp_topk_tau(sp, NSTEP_P, qv.x, qv.y, qv.z, lane, 15);
    warp_cov_store(sp, NSTEP_P, qv.x, qv.y, qv.z, lane, tau,
                   g_cov_patch + (size_t)gq * 6);
}

// ---------------------------------------------------------------------------
// Loss: eigen(cov) x2 per point, norm of abs-diff, mean.
// ---------------------------------------------------------------------------
__global__ void zero_out_kernel(float* out) { out[0] = 0.0f; }

__global__ void __launch_bounds__(256)
loss_kernel(float* __restrict__ out)
{
    const int i = blockIdx.x * 256 + threadIdx.x;
    float v = 0.0f;
    if (i < TOTAL_PTS) {
        float ng[3], np_[3];
        smallest_evec_abs(g_cov_global + (size_t)i * 6, ng);
        smallest_evec_abs(g_cov_patch  + (size_t)i * 6, np_);
        float dx = np_[0] - ng[0];
        float dy = np_[1] - ng[1];
        float dz = np_[2] - ng[2];
        v = sqrtf(fmaf(dx, dx, fmaf(dy, dy, dz * dz)));
    }
#pragma unroll
    for (int off = 16; off > 0; off >>= 1)
        v += __shfl_down_sync(0xFFFFFFFFu, v, off);

    __shared__ float warpsum[8];
    const int lane = threadIdx.x & 31;
    const int wid  = threadIdx.x >> 5;
    if (lane == 0) warpsum[wid] = v;
    __syncthreads();

    if (wid == 0) {
        float s = (lane < 8) ? warpsum[lane] : 0.0f;
#pragma unroll
        for (int off = 4; off > 0; off >>= 1)
            s += __shfl_down_sync(0xFFFFFFFFu, s, off);
        if (lane == 0)
            atomicAdd(out, s * (1.0f / (float)TOTAL_PTS));
    }
}

// ---------------------------------------------------------------------------
extern "C" void kernel_launch(void* const* d_in, const int* in_sizes, int n_in,
                              void* d_out, int out_size)
{
    const float* pc = (const float*)d_in[0];
    float* out = (float*)d_out;

    zero_out_kernel<<<1, 1>>>(out);

    dim3 gGrid((NPTS + WPB - 1) / WPB, BATCH);   // (157, 8)
    knn_global_kernel<<<gGrid, 512>>>(pc);

    knn_patch_kernel<<<TOTAL_PTS / WPB, 512>>>(pc);   // 1250 blocks

    loss_kernel<<<(TOTAL_PTS + 255) / 256, 256>>>(out);
}

// round 6
// speedup vs baseline: 52.5740x; 1.0847x over previous
#include <cuda_runtime.h>
#include <cuda_bf16.h>
#include <math_constants.h>
#include <cfloat>

#define BATCH 8
#define NPTS 2500
#define NUM_PATCHES 25
#define PATCH_P 100
#define TOTAL_PTS (BATCH * NPTS)             // 20000
#define TOTAL_PATCHES (BATCH * NUM_PATCHES)  // 200

#define WPB 16                 // warps (=queries) per block
#define NSTEP_G 79             // ceil(2500/32)
#define NPAD_G (NSTEP_G * 32)  // 2528
#define NSTEP_P 4              // patch padded to 128

#define GBLK_PER_B 157                      // ceil(2500/16)
#define GBLKS (GBLK_PER_B * BATCH)          // 1256 global blocks
#define PBLKS (TOTAL_PTS / WPB)             // 1250 patch blocks
#define FUSED_BLKS (GBLKS + PBLKS)          // 2506

__device__ float g_cov_global[TOTAL_PTS * 6];
__device__ float g_cov_patch[TOTAL_PTS * 6];

// ---------------------------------------------------------------------------
// 3x3 symmetric smallest-eigenvector (double), writes |v|.
// ---------------------------------------------------------------------------
__device__ __forceinline__ void smallest_evec_abs(
    const float* s, float out[3])
{
    double a00 = s[0], a01 = s[1], a02 = s[2];
    double a11 = s[3], a12 = s[4], a22 = s[5];

    double p1 = a01 * a01 + a02 * a02 + a12 * a12;
    double q  = (a00 + a11 + a22) * (1.0 / 3.0);
    double d0 = a00 - q, d1 = a11 - q, d2 = a22 - q;
    double p2 = d0 * d0 + d1 * d1 + d2 * d2 + 2.0 * p1;

    double lam;
    if (p2 <= 1e-300) {
        lam = q;
    } else {
        double p   = sqrt(p2 * (1.0 / 6.0));
        double inv = 1.0 / p;
        double b00 = d0 * inv, b11 = d1 * inv, b22 = d2 * inv;
        double b01 = a01 * inv, b02 = a02 * inv, b12 = a12 * inv;
        double detB = b00 * (b11 * b22 - b12 * b12)
                    - b01 * (b01 * b22 - b12 * b02)
                    + b02 * (b01 * b12 - b11 * b02);
        double r = 0.5 * detB;
        r = fmin(1.0, fmax(-1.0, r));
        double phi = acos(r) * (1.0 / 3.0);
        lam = q + 2.0 * p * cos(phi + 2.0943951023931953);
    }

    double r0x = a00 - lam, r0y = a01,       r0z = a02;
    double r1x = a01,       r1y = a11 - lam, r1z = a12;
    double r2x = a02,       r2y = a12,       r2z = a22 - lam;

    double c0x = r0y * r1z - r0z * r1y;
    double c0y = r0z * r1x - r0x * r1z;
    double c0z = r0x * r1y - r0y * r1x;

    double c1x = r0y * r2z - r0z * r2y;
    double c1y = r0z * r2x - r0x * r2z;
    double c1z = r0x * r2y - r0y * r2x;

    double c2x = r1y * r2z - r1z * r2y;
    double c2y = r1z * r2x - r1x * r2z;
    double c2z = r1x * r2y - r1y * r2x;

    double n0 = c0x * c0x + c0y * c0y + c0z * c0z;
    double n1 = c1x * c1x + c1y * c1y + c1z * c1z;
    double n2 = c2x * c2x + c2y * c2y + c2z * c2z;

    double vx = c0x, vy = c0y, vz = c0z, nn = n0;
    if (n1 > nn) { vx = c1x; vy = c1y; vz = c1z; nn = n1; }
    if (n2 > nn) { vx = c2x; vy = c2y; vz = c2z; nn = n2; }
    if (nn < 1e-300) { vx = 1.0; vy = 0.0; vz = 0.0; nn = 1.0; }

    double invn = rsqrt(nn);
    out[0] = (float)fabs(vx * invn);
    out[1] = (float)fabs(vy * invn);
    out[2] = (float)fabs(vz * invn);
}

// ---------------------------------------------------------------------------
// Warp-distributed exact k-th smallest key (sorted-32 across lanes).
// sp padded to nstep*32 entries with w = FLT_MAX sentinels.
// ---------------------------------------------------------------------------
__device__ __forceinline__ float warp_topk_tau(
    const float4* __restrict__ sp, int nstep,
    float qx, float qy, float qz, int lane, int tauLane)
{
    const unsigned FULL = 0xFFFFFFFFu;
    float v   = CUDART_INF_F;
    float tau = CUDART_INF_F;

    for (int n = 0; n < nstep; ++n) {
        float4 p = sp[n * 32 + lane];
        float dot = fmaf(qx, p.x, fmaf(qy, p.y, qz * p.z));
        float key = fmaf(-2.0f, dot, p.w);

        unsigned mask = __ballot_sync(FULL, key < tau);
        if (mask) {
            if (__popc(mask) <= 8) {
                // serial sorted insertions
                do {
                    int src = __ffs(mask) - 1;
                    mask &= mask - 1;
                    float k  = __shfl_sync(FULL, key, src);
                    float vp = __shfl_up_sync(FULL, v, 1);
                    if (lane == 0) vp = -CUDART_INF_F;
                    v = (v < k) ? v : ((vp < k) ? k : vp);
                } while (mask);
            } else {
                // bitonic sort the 32 candidate keys ascending
#pragma unroll
                for (int size = 2; size <= 32; size <<= 1) {
#pragma unroll
                    for (int stride = size >> 1; stride > 0; stride >>= 1) {
                        float o = __shfl_xor_sync(FULL, key, stride);
                        bool mn = ((lane & size) == 0) == ((lane & stride) == 0);
                        key = mn ? fminf(key, o) : fmaxf(key, o);
                    }
                }
                // keep lowest 32 of union, clean to ascending
                float r = __shfl_sync(FULL, key, 31 - lane);
                v = fminf(v, r);
#pragma unroll
                for (int stride = 16; stride > 0; stride >>= 1) {
                    float o = __shfl_xor_sync(FULL, v, stride);
                    v = ((lane & stride) == 0) ? fminf(v, o) : fmaxf(v, o);
                }
            }
            tau = __shfl_sync(FULL, v, tauLane);
        }
    }
    return tau;
}

// Rescan with warp-uniform hit skipping; lane0 stores covariance.
__device__ __forceinline__ void warp_cov_store(
    const float4* __restrict__ sp, int nstep,
    float qx, float qy, float qz, int lane, float tau, float* __restrict__ cb)
{
    const unsigned FULL = 0xFFFFFFFFu;
    float xx = 0.f, xy = 0.f, xz = 0.f, yy = 0.f, yz = 0.f, zz = 0.f;
    for (int n = 0; n < nstep; ++n) {
        float4 p = sp[n * 32 + lane];
        float dot = fmaf(qx, p.x, fmaf(qy, p.y, qz * p.z));
        float key = fmaf(-2.0f, dot, p.w);
        bool hit = (key <= tau);
        if (__ballot_sync(FULL, hit)) {
            if (hit) {
                float dx = p.x - qx, dy = p.y - qy, dz = p.z - qz;
                xx = fmaf(dx, dx, xx);
                xy = fmaf(dx, dy, xy);
                xz = fmaf(dx, dz, xz);
                yy = fmaf(dy, dy, yy);
                yz = fmaf(dy, dz, yz);
                zz = fmaf(dz, dz, zz);
            }
        }
    }
#pragma unroll
    for (int off = 16; off > 0; off >>= 1) {
        xx += __shfl_xor_sync(FULL, xx, off);
        xy += __shfl_xor_sync(FULL, xy, off);
        xz += __shfl_xor_sync(FULL, xz, off);
        yy += __shfl_xor_sync(FULL, yy, off);
        yz += __shfl_xor_sync(FULL, yz, off);
        zz += __shfl_xor_sync(FULL, zz, off);
    }
    if (lane == 0) {
        cb[0] = xx; cb[1] = xy; cb[2] = xz;
        cb[3] = yy; cb[4] = yz; cb[5] = zz;
    }
}

// ---------------------------------------------------------------------------
// Fused kNN kernel. Blocks [0, GBLKS): global 32-NN. Blocks [GBLKS, ...):
// patch 16-NN. Block 0 also zeroes the output accumulator (runs before loss).
// ---------------------------------------------------------------------------
__global__ void __launch_bounds__(512, 4)
knn_fused_kernel(const float* __restrict__ pc, float* __restrict__ out)
{
    __shared__ float4 sp[NPAD_G];   // 40448 B

    const int warp = threadIdx.x >> 5;
    const int lane = threadIdx.x & 31;

    if (blockIdx.x == 0 && threadIdx.x == 0) out[0] = 0.0f;

    if (blockIdx.x < GBLKS) {
        // -------- global 32-NN --------
        const int b  = blockIdx.x / GBLK_PER_B;
        const int qb = blockIdx.x % GBLK_PER_B;
        const float* base = pc + (size_t)b * NPTS * 3;

        for (int j = threadIdx.x; j < NPAD_G; j += 512) {
            float4 val = make_float4(0.f, 0.f, 0.f, FLT_MAX);
            if (j < NPTS) {
                float x = base[3 * j + 0];
                float y = base[3 * j + 1];
                float z = base[3 * j + 2];
                val = make_float4(x, y, z, fmaf(x, x, fmaf(y, y, z * z)));
            }
            sp[j] = val;
        }
        __syncthreads();

        const int q = qb * WPB + warp;
        if (q >= NPTS) return;

        const float4 qv = sp[q];
        float tau = warp_topk_tau(sp, NSTEP_G, qv.x, qv.y, qv.z, lane, 31);
        warp_cov_store(sp, NSTEP_G, qv.x, qv.y, qv.z, lane, tau,
                       g_cov_global + (size_t)(b * NPTS + q) * 6);
    } else {
        // -------- patch 16-NN: 16 queries spanning <= 2 patches --------
        const int pblk = blockIdx.x - GBLKS;
        const int q0 = pblk * WPB;
        const int p0 = q0 / PATCH_P;

        for (int t = threadIdx.x; t < 256; t += 512) {
            const int which = t >> 7;
            const int local = t & 127;
            const int pp = p0 + which;
            float4 val = make_float4(0.f, 0.f, 0.f, FLT_MAX);
            if (local < PATCH_P && pp < TOTAL_PATCHES) {
                const float* bb = pc + (size_t)pp * PATCH_P * 3;
                float x = bb[3 * local + 0];
                float y = bb[3 * local + 1];
                float z = bb[3 * local + 2];
                val = make_float4(x, y, z, fmaf(x, x, fmaf(y, y, z * z)));
            }
            sp[(which << 7) + local] = val;
        }
        __syncthreads();

        const int gq = q0 + warp;
        const int pp = gq / PATCH_P;
        const int ql = gq % PATCH_P;
        const float4* spl = sp + ((pp - p0) << 7);

        const float4 qv = spl[ql];
        float tau = warp_topk_tau(spl, NSTEP_P, qv.x, qv.y, qv.z, lane, 15);
        warp_cov_store(spl, NSTEP_P, qv.x, qv.y, qv.z, lane, tau,
                       g_cov_patch + (size_t)gq * 6);
    }
}

// ---------------------------------------------------------------------------
// Loss: eigen(cov) x2 per point, norm of abs-diff, mean. 157 x 128.
// ---------------------------------------------------------------------------
__global__ void __launch_bounds__(128)
loss_kernel(float* __restrict__ out)
{
    const int i = blockIdx.x * 128 + threadIdx.x;
    float v = 0.0f;
    if (i < TOTAL_PTS) {
        float ng[3], np_[3];
        smallest_evec_abs(g_cov_global + (size_t)i * 6, ng);
        smallest_evec_abs(g_cov_patch  + (size_t)i * 6, np_);
        float dx = np_[0] - ng[0];
        float dy = np_[1] - ng[1];
        float dz = np_[2] - ng[2];
        v = sqrtf(fmaf(dx, dx, fmaf(dy, dy, dz * dz)));
    }
#pragma unroll
    for (int off = 16; off > 0; off >>= 1)
        v += __shfl_down_sync(0xFFFFFFFFu, v, off);

    __shared__ float warpsum[4];
    const int lane = threadIdx.x & 31;
    const int wid  = threadIdx.x >> 5;
    if (lane == 0) warpsum[wid] = v;
    __syncthreads();

    if (wid == 0) {
        float s = (lane < 4) ? warpsum[lane] : 0.0f;
#pragma unroll
        for (int off = 2; off > 0; off >>= 1)
            s += __shfl_down_sync(0xFFFFFFFFu, s, off);
        if (lane == 0)
            atomicAdd(out, s * (1.0f / (float)TOTAL_PTS));
    }
}

// ---------------------------------------------------------------------------
extern "C" void kernel_launch(void* const* d_in, const int* in_sizes, int n_in,
                              void* d_out, int out_size)
{
    const float* pc = (const float*)d_in[0];
    float* out = (float*)d_out;

    knn_fused_kernel<<<FUSED_BLKS, 512>>>(pc, out);
    loss_kernel<<<(TOTAL_PTS + 127) / 128, 128>>>(out);
}

// round 7
// speedup vs baseline: 69.2381x; 1.3170x over previous
#include <cuda_runtime.h>
#include <cuda_bf16.h>
#include <math_constants.h>
#include <cfloat>

#define BATCH 8
#define NPTS 2500
#define NUM_PATCHES 25
#define PATCH_P 100
#define TOTAL_PTS (BATCH * NPTS)             // 20000
#define TOTAL_PATCHES (BATCH * NUM_PATCHES)  // 200

#define WPB 16                 // warps (=queries) per block
#define NSTEP_G 79             // ceil(2500/32)
#define NPAD_G (NSTEP_G * 32)  // 2528
#define NSTEP_P 4              // patch padded to 128

#define GBLK_PER_B 157                      // ceil(2500/16)
#define GBLKS (GBLK_PER_B * BATCH)          // 1256
#define PBLKS (TOTAL_PTS / WPB)             // 1250
#define FUSED_BLKS (GBLKS + PBLKS)          // 2506

__device__ float g_cov_global[TOTAL_PTS * 6];
__device__ float g_cov_patch[TOTAL_PTS * 6];

// ---------------------------------------------------------------------------
// 3x3 symmetric smallest-eigenvector (double), writes |v|.
// ---------------------------------------------------------------------------
__device__ __forceinline__ void smallest_evec_abs(
    const float* s, float out[3])
{
    double a00 = s[0], a01 = s[1], a02 = s[2];
    double a11 = s[3], a12 = s[4], a22 = s[5];

    double p1 = a01 * a01 + a02 * a02 + a12 * a12;
    double q  = (a00 + a11 + a22) * (1.0 / 3.0);
    double d0 = a00 - q, d1 = a11 - q, d2 = a22 - q;
    double p2 = d0 * d0 + d1 * d1 + d2 * d2 + 2.0 * p1;

    double lam;
    if (p2 <= 1e-300) {
        lam = q;
    } else {
        double p   = sqrt(p2 * (1.0 / 6.0));
        double inv = 1.0 / p;
        double b00 = d0 * inv, b11 = d1 * inv, b22 = d2 * inv;
        double b01 = a01 * inv, b02 = a02 * inv, b12 = a12 * inv;
        double detB = b00 * (b11 * b22 - b12 * b12)
                    - b01 * (b01 * b22 - b12 * b02)
                    + b02 * (b01 * b12 - b11 * b02);
        double r = 0.5 * detB;
        r = fmin(1.0, fmax(-1.0, r));
        double phi = acos(r) * (1.0 / 3.0);
        lam = q + 2.0 * p * cos(phi + 2.0943951023931953);
    }

    double r0x = a00 - lam, r0y = a01,       r0z = a02;
    double r1x = a01,       r1y = a11 - lam, r1z = a12;
    double r2x = a02,       r2y = a12,       r2z = a22 - lam;

    double c0x = r0y * r1z - r0z * r1y;
    double c0y = r0z * r1x - r0x * r1z;
    double c0z = r0x * r1y - r0y * r1x;

    double c1x = r0y * r2z - r0z * r2y;
    double c1y = r0z * r2x - r0x * r2z;
    double c1z = r0x * r2y - r0y * r2x;

    double c2x = r1y * r2z - r1z * r2y;
    double c2y = r1z * r2x - r1x * r2z;
    double c2z = r1x * r2y - r1y * r2x;

    double n0 = c0x * c0x + c0y * c0y + c0z * c0z;
    double n1 = c1x * c1x + c1y * c1y + c1z * c1z;
    double n2 = c2x * c2x + c2y * c2y + c2z * c2z;

    double vx = c0x, vy = c0y, vz = c0z, nn = n0;
    if (n1 > nn) { vx = c1x; vy = c1y; vz = c1z; nn = n1; }
    if (n2 > nn) { vx = c2x; vy = c2y; vz = c2z; nn = n2; }
    if (nn < 1e-300) { vx = 1.0; vy = 0.0; vz = 0.0; nn = 1.0; }

    double invn = rsqrt(nn);
    out[0] = (float)fabs(vx * invn);
    out[1] = (float)fabs(vy * invn);
    out[2] = (float)fabs(vz * invn);
}

// monotonic float->uint map (order-preserving, incl. negatives)
__device__ __forceinline__ unsigned fkey(float f)
{
    unsigned u = __float_as_uint(f);
    return u ^ (unsigned)(((int)u >> 31) | 0x80000000);
}

// pack: truncated monotone key | 12-bit candidate index
__device__ __forceinline__ unsigned pack_key(float f, int j)
{
    return (fkey(f) & 0xFFFFF000u) | (unsigned)j;
}

// ascending bitonic sort of 32 uints across lanes
__device__ __forceinline__ unsigned sort32(unsigned ku, int lane)
{
    const unsigned FULL = 0xFFFFFFFFu;
#pragma unroll
    for (int size = 2; size <= 32; size <<= 1) {
#pragma unroll
        for (int stride = size >> 1; stride > 0; stride >>= 1) {
            unsigned o = __shfl_xor_sync(FULL, ku, stride);
            bool mn = ((lane & size) == 0) == ((lane & stride) == 0);
            ku = mn ? umin(ku, o) : umax(ku, o);
        }
    }
    return ku;
}

// ---------------------------------------------------------------------------
// Warp-distributed selection of the K smallest packed keys (K <= 32).
// Maintains 32 smallest-so-far sorted ascending across lanes; threshold is
// slot K-1. Returns the packed key held by this lane (lane l = l-th member
// for l < K). sp padded to nstep*32 entries with w = FLT_MAX sentinels.
// ---------------------------------------------------------------------------
template <int K>
__device__ __forceinline__ unsigned warp_select(
    const float4* __restrict__ sp, int nstep,
    float qx, float qy, float qz, int lane)
{
    const unsigned FULL = 0xFFFFFFFFu;

    // step 0: straight sort of the first 32 candidates
    float4 p0 = sp[lane];
    float k0 = fmaf(-2.0f, fmaf(qx, p0.x, fmaf(qy, p0.y, qz * p0.z)), p0.w);
    unsigned v = sort32(pack_key(k0, lane), lane);
    unsigned tau = __shfl_sync(FULL, v, K - 1);

    for (int n = 1; n < nstep; ++n) {
        const int j = n * 32 + lane;
        float4 p = sp[j];
        float kf = fmaf(-2.0f, fmaf(qx, p.x, fmaf(qy, p.y, qz * p.z)), p.w);
        unsigned ku = pack_key(kf, j);

        unsigned mask = __ballot_sync(FULL, ku < tau);
        if (mask) {
            if (__popc(mask) <= 8) {
                // serial sorted insertions
                do {
                    int src = __ffs(mask) - 1;
                    mask &= mask - 1;
                    unsigned k  = __shfl_sync(FULL, ku, src);
                    unsigned vp = __shfl_up_sync(FULL, v, 1);
                    if (lane == 0) vp = 0u;
                    v = (v < k) ? v : ((vp < k) ? k : vp);
                } while (mask);
            } else {
                unsigned s = sort32(ku, lane);
                unsigned r = __shfl_sync(FULL, s, 31 - lane);
                v = umin(v, r);
#pragma unroll
                for (int stride = 16; stride > 0; stride >>= 1) {
                    unsigned o = __shfl_xor_sync(FULL, v, stride);
                    v = ((lane & stride) == 0) ? umin(v, o) : umax(v, o);
                }
            }
            tau = __shfl_sync(FULL, v, K - 1);
        }
    }
    return v;
}

// Covariance of the K selected neighbors (query-centered), via direct gather.
template <int K>
__device__ __forceinline__ void warp_cov_gather_store(
    const float4* __restrict__ sp, unsigned v,
    float qx, float qy, float qz, int lane, float* __restrict__ cb)
{
    const unsigned FULL = 0xFFFFFFFFu;
    float xx = 0.f, xy = 0.f, xz = 0.f, yy = 0.f, yz = 0.f, zz = 0.f;

    float4 m = sp[v & 0xFFFu];
    if (lane < K) {
        float dx = m.x - qx, dy = m.y - qy, dz = m.z - qz;
        xx = dx * dx; xy = dx * dy; xz = dx * dz;
        yy = dy * dy; yz = dy * dz; zz = dz * dz;
    }
#pragma unroll
    for (int off = 16; off > 0; off >>= 1) {
        xx += __shfl_xor_sync(FULL, xx, off);
        xy += __shfl_xor_sync(FULL, xy, off);
        xz += __shfl_xor_sync(FULL, xz, off);
        yy += __shfl_xor_sync(FULL, yy, off);
        yz += __shfl_xor_sync(FULL, yz, off);
        zz += __shfl_xor_sync(FULL, zz, off);
    }
    if (lane == 0) {
        cb[0] = xx; cb[1] = xy; cb[2] = xz;
        cb[3] = yy; cb[4] = yz; cb[5] = zz;
    }
}

// ---------------------------------------------------------------------------
// Fused kNN kernel. Blocks [0, GBLKS): global 32-NN. Rest: patch 16-NN.
// Block 0 also zeroes the output accumulator (stream order precedes loss).
// ---------------------------------------------------------------------------
__global__ void __launch_bounds__(512, 4)
knn_fused_kernel(const float* __restrict__ pc, float* __restrict__ out)
{
    __shared__ float4 sp[NPAD_G];   // 40448 B

    const int warp = threadIdx.x >> 5;
    const int lane = threadIdx.x & 31;

    if (blockIdx.x == 0 && threadIdx.x == 0) out[0] = 0.0f;

    if (blockIdx.x < GBLKS) {
        // -------- global 32-NN --------
        const int b  = blockIdx.x / GBLK_PER_B;
        const int qb = blockIdx.x % GBLK_PER_B;
        const float* base = pc + (size_t)b * NPTS * 3;

        for (int j = threadIdx.x; j < NPAD_G; j += 512) {
            float4 val = make_float4(0.f, 0.f, 0.f, FLT_MAX);
            if (j < NPTS) {
                float x = base[3 * j + 0];
                float y = base[3 * j + 1];
                float z = base[3 * j + 2];
                val = make_float4(x, y, z, fmaf(x, x, fmaf(y, y, z * z)));
            }
            sp[j] = val;
        }
        __syncthreads();

        const int q = qb * WPB + warp;
        if (q >= NPTS) return;

        const float4 qv = sp[q];
        unsigned v = warp_select<32>(sp, NSTEP_G, qv.x, qv.y, qv.z, lane);
        warp_cov_gather_store<32>(sp, v, qv.x, qv.y, qv.z, lane,
                                  g_cov_global + (size_t)(b * NPTS + q) * 6);
    } else {
        // -------- patch 16-NN: 16 queries spanning <= 2 patches --------
        const int pblk = blockIdx.x - GBLKS;
        const int q0 = pblk * WPB;
        const int p0 = q0 / PATCH_P;

        for (int t = threadIdx.x; t < 256; t += 512) {
            const int which = t >> 7;
            const int local = t & 127;
            const int pp = p0 + which;
            float4 val = make_float4(0.f, 0.f, 0.f, FLT_MAX);
            if (local < PATCH_P && pp < TOTAL_PATCHES) {
                const float* bb = pc + (size_t)pp * PATCH_P * 3;
                float x = bb[3 * local + 0];
                float y = bb[3 * local + 1];
                float z = bb[3 * local + 2];
                val = make_float4(x, y, z, fmaf(x, x, fmaf(y, y, z * z)));
            }
            sp[(which << 7) + local] = val;
        }
        __syncthreads();

        const int gq = q0 + warp;
        const int pp = gq / PATCH_P;
        const int ql = gq % PATCH_P;
        const float4* spl = sp + ((pp - p0) << 7);

        const float4 qv = spl[ql];
        unsigned v = warp_select<16>(spl, NSTEP_P, qv.x, qv.y, qv.z, lane);
        warp_cov_gather_store<16>(spl, v, qv.x, qv.y, qv.z, lane,
                                  g_cov_patch + (size_t)gq * 6);
    }
}

// ---------------------------------------------------------------------------
// Loss: one eigen per thread (even lanes: global, odd: patch), pair-combine
// via shfl, mean-reduce. 313 blocks x 128 threads -> 64 points per block.
// ---------------------------------------------------------------------------
__global__ void __launch_bounds__(128)
loss_kernel(float* __restrict__ out)
{
    const int t = blockIdx.x * 128 + threadIdx.x;
    const int i = t >> 1;               // point id
    const int which = t & 1;            // 0 = global, 1 = patch

    float v = 0.0f;
    if (i < TOTAL_PTS) {
        const float* cb = which ? (g_cov_patch  + (size_t)i * 6)
                                : (g_cov_global + (size_t)i * 6);
        float nv[3];
        smallest_evec_abs(cb, nv);
        // partner (other eigen of the same point) sits in the adjacent lane
        float ox = __shfl_xor_sync(0xFFFFFFFFu, nv[0], 1);
        float oy = __shfl_xor_sync(0xFFFFFFFFu, nv[1], 1);
        float oz = __shfl_xor_sync(0xFFFFFFFFu, nv[2], 1);
        if (which == 0) {
            float dx = ox - nv[0], dy = oy - nv[1], dz = oz - nv[2];
            v = sqrtf(fmaf(dx, dx, fmaf(dy, dy, dz * dz)));
        }
    }
#pragma unroll
    for (int off = 16; off > 0; off >>= 1)
        v += __shfl_down_sync(0xFFFFFFFFu, v, off);

    __shared__ float warpsum[4];
    const int lane = threadIdx.x & 31;
    const int wid  = threadIdx.x >> 5;
    if (lane == 0) warpsum[wid] = v;
    __syncthreads();

    if (wid == 0) {
        float s = (lane < 4) ? warpsum[lane] : 0.0f;
#pragma unroll
        for (int off = 2; off > 0; off >>= 1)
            s += __shfl_down_sync(0xFFFFFFFFu, s, off);
        if (lane == 0)
            atomicAdd(out, s * (1.0f / (float)TOTAL_PTS));
    }
}

// ---------------------------------------------------------------------------
extern "C" void kernel_launch(void* const* d_in, const int* in_sizes, int n_in,
                              void* d_out, int out_size)
{
    const float* pc = (const float*)d_in[0];
    float* out = (float*)d_out;

    knn_fused_kernel<<<FUSED_BLKS, 512>>>(pc, out);
    loss_kernel<<<(2 * TOTAL_PTS + 127) / 128, 128>>>(out);
}

// round 8
// speedup vs baseline: 72.4453x; 1.0463x over previous
#include <cuda_runtime.h>
#include <cuda_bf16.h>
#include <math_constants.h>
#include <cfloat>

#define BATCH 8
#define NPTS 2500
#define NUM_PATCHES 25
#define PATCH_P 100
#define TOTAL_PTS (BATCH * NPTS)             // 20000
#define TOTAL_PATCHES (BATCH * NUM_PATCHES)  // 200

#define WPB 16                 // warps (=queries) per block
#define NSTEP_G 79             // ceil(2500/32)
#define NPAD_G (NSTEP_G * 32)  // 2528
#define NSTEP_P 4              // patch padded to 128

#define GBLK_PER_B 157                      // ceil(2500/16)
#define GBLKS (GBLK_PER_B * BATCH)          // 1256
#define PBLKS (TOTAL_PTS / WPB)             // 1250
#define FUSED_BLKS (GBLKS + PBLKS)          // 2506

#define PAD_COORD 1.0e18f      // padded points: d^2 overflows to +inf

__device__ float g_cov_global[TOTAL_PTS * 6];
__device__ float g_cov_patch[TOTAL_PTS * 6];

// ---------------------------------------------------------------------------
// 3x3 symmetric smallest-eigenvector (double), writes |v|.
// ---------------------------------------------------------------------------
__device__ __forceinline__ void smallest_evec_abs(
    const float* s, float out[3])
{
    double a00 = s[0], a01 = s[1], a02 = s[2];
    double a11 = s[3], a12 = s[4], a22 = s[5];

    double p1 = a01 * a01 + a02 * a02 + a12 * a12;
    double q  = (a00 + a11 + a22) * (1.0 / 3.0);
    double d0 = a00 - q, d1 = a11 - q, d2 = a22 - q;
    double p2 = d0 * d0 + d1 * d1 + d2 * d2 + 2.0 * p1;

    double lam;
    if (p2 <= 1e-300) {
        lam = q;
    } else {
        double p   = sqrt(p2 * (1.0 / 6.0));
        double inv = 1.0 / p;
        double b00 = d0 * inv, b11 = d1 * inv, b22 = d2 * inv;
        double b01 = a01 * inv, b02 = a02 * inv, b12 = a12 * inv;
        double detB = b00 * (b11 * b22 - b12 * b12)
                    - b01 * (b01 * b22 - b12 * b02)
                    + b02 * (b01 * b12 - b11 * b02);
        double r = 0.5 * detB;
        r = fmin(1.0, fmax(-1.0, r));
        double phi = acos(r) * (1.0 / 3.0);
        lam = q + 2.0 * p * cos(phi + 2.0943951023931953);
    }

    double r0x = a00 - lam, r0y = a01,       r0z = a02;
    double r1x = a01,       r1y = a11 - lam, r1z = a12;
    double r2x = a02,       r2y = a12,       r2z = a22 - lam;

    double c0x = r0y * r1z - r0z * r1y;
    double c0y = r0z * r1x - r0x * r1z;
    double c0z = r0x * r1y - r0y * r1x;

    double c1x = r0y * r2z - r0z * r2y;
    double c1y = r0z * r2x - r0x * r2z;
    double c1z = r0x * r2y - r0y * r2x;

    double c2x = r1y * r2z - r1z * r2y;
    double c2y = r1z * r2x - r1x * r2z;
    double c2z = r1x * r2y - r1y * r2x;

    double n0 = c0x * c0x + c0y * c0y + c0z * c0z;
    double n1 = c1x * c1x + c1y * c1y + c1z * c1z;
    double n2 = c2x * c2x + c2y * c2y + c2z * c2z;

    double vx = c0x, vy = c0y, vz = c0z, nn = n0;
    if (n1 > nn) { vx = c1x; vy = c1y; vz = c1z; nn = n1; }
    if (n2 > nn) { vx = c2x; vy = c2y; vz = c2z; nn = n2; }
    if (nn < 1e-300) { vx = 1.0; vy = 0.0; vz = 0.0; nn = 1.0; }

    double invn = rsqrt(nn);
    out[0] = (float)fabs(vx * invn);
    out[1] = (float)fabs(vy * invn);
    out[2] = (float)fabs(vz * invn);
}

// pack: d^2 is non-negative -> its float bits are order-preserving as
// unsigned. Truncate low 12 mantissa bits, OR in the candidate index.
__device__ __forceinline__ unsigned pack_key(float d2, int j)
{
    return (__float_as_uint(d2) & 0xFFFFF000u) | (unsigned)j;
}

// ascending bitonic sort of 32 uints across lanes
__device__ __forceinline__ unsigned sort32(unsigned ku, int lane)
{
    const unsigned FULL = 0xFFFFFFFFu;
#pragma unroll
    for (int size = 2; size <= 32; size <<= 1) {
#pragma unroll
        for (int stride = size >> 1; stride > 0; stride >>= 1) {
            unsigned o = __shfl_xor_sync(FULL, ku, stride);
            bool mn = ((lane & size) == 0) == ((lane & stride) == 0);
            ku = mn ? umin(ku, o) : umax(ku, o);
        }
    }
    return ku;
}

// squared distance to the query (direct form: small absolute quantization
// at the selection boundary, unlike |p|^2 - 2 q.p)
__device__ __forceinline__ float qdist2(float4 p, float qx, float qy, float qz)
{
    float dx = p.x - qx, dy = p.y - qy, dz = p.z - qz;
    return fmaf(dx, dx, fmaf(dy, dy, dz * dz));
}

// ---------------------------------------------------------------------------
// Warp-distributed selection of the K smallest packed keys (K <= 32).
// Maintains 32 smallest-so-far sorted ascending across lanes; threshold is
// slot K-1. Lane l ends holding the l-th member (l < K).
// sp padded with PAD_COORD points (d^2 = +inf).
// ---------------------------------------------------------------------------
template <int K>
__device__ __forceinline__ unsigned warp_select(
    const float4* __restrict__ sp, int nstep,
    float qx, float qy, float qz, int lane)
{
    const unsigned FULL = 0xFFFFFFFFu;

    // step 0: straight sort of the first 32 candidates
    float k0 = qdist2(sp[lane], qx, qy, qz);
    unsigned v = sort32(pack_key(k0, lane), lane);
    unsigned tau = __shfl_sync(FULL, v, K - 1);

    for (int n = 1; n < nstep; ++n) {
        const int j = n * 32 + lane;
        float kf = qdist2(sp[j], qx, qy, qz);
        unsigned ku = pack_key(kf, j);

        unsigned mask = __ballot_sync(FULL, ku < tau);
        if (mask) {
            if (__popc(mask) <= 8) {
                // serial sorted insertions
                do {
                    int src = __ffs(mask) - 1;
                    mask &= mask - 1;
                    unsigned k  = __shfl_sync(FULL, ku, src);
                    unsigned vp = __shfl_up_sync(FULL, v, 1);
                    if (lane == 0) vp = 0u;
                    v = (v < k) ? v : ((vp < k) ? k : vp);
                } while (mask);
            } else {
                unsigned s = sort32(ku, lane);
                unsigned r = __shfl_sync(FULL, s, 31 - lane);
                v = umin(v, r);
#pragma unroll
                for (int stride = 16; stride > 0; stride >>= 1) {
                    unsigned o = __shfl_xor_sync(FULL, v, stride);
                    v = ((lane & stride) == 0) ? umin(v, o) : umax(v, o);
                }
            }
            tau = __shfl_sync(FULL, v, K - 1);
        }
    }
    return v;
}

// Covariance of the K selected neighbors (query-centered), via direct gather.
template <int K>
__device__ __forceinline__ void warp_cov_gather_store(
    const float4* __restrict__ sp, unsigned v,
    float qx, float qy, float qz, int lane, float* __restrict__ cb)
{
    const unsigned FULL = 0xFFFFFFFFu;
    float xx = 0.f, xy = 0.f, xz = 0.f, yy = 0.f, yz = 0.f, zz = 0.f;

    float4 m = sp[v & 0xFFFu];
    if (lane < K) {
        float dx = m.x - qx, dy = m.y - qy, dz = m.z - qz;
        xx = dx * dx; xy = dx * dy; xz = dx * dz;
        yy = dy * dy; yz = dy * dz; zz = dz * dz;
    }
#pragma unroll
    for (int off = 16; off > 0; off >>= 1) {
        xx += __shfl_xor_sync(FULL, xx, off);
        xy += __shfl_xor_sync(FULL, xy, off);
        xz += __shfl_xor_sync(FULL, xz, off);
        yy += __shfl_xor_sync(FULL, yy, off);
        yz += __shfl_xor_sync(FULL, yz, off);
        zz += __shfl_xor_sync(FULL, zz, off);
    }
    if (lane == 0) {
        cb[0] = xx; cb[1] = xy; cb[2] = xz;
        cb[3] = yy; cb[4] = yz; cb[5] = zz;
    }
}

// ---------------------------------------------------------------------------
// Fused kNN kernel. Blocks [0, GBLKS): global 32-NN. Rest: patch 16-NN.
// Block 0 also zeroes the output accumulator (stream order precedes loss).
// ---------------------------------------------------------------------------
__global__ void __launch_bounds__(512, 4)
knn_fused_kernel(const float* __restrict__ pc, float* __restrict__ out)
{
    __shared__ float4 sp[NPAD_G];   // 40448 B

    const int warp = threadIdx.x >> 5;
    const int lane = threadIdx.x & 31;

    if (blockIdx.x == 0 && threadIdx.x == 0) out[0] = 0.0f;

    if (blockIdx.x < GBLKS) {
        // -------- global 32-NN --------
        const int b  = blockIdx.x / GBLK_PER_B;
        const int qb = blockIdx.x % GBLK_PER_B;
        const float* base = pc + (size_t)b * NPTS * 3;

        for (int j = threadIdx.x; j < NPAD_G; j += 512) {
            float4 val = make_float4(PAD_COORD, PAD_COORD, PAD_COORD, 0.f);
            if (j < NPTS) {
                val = make_float4(base[3 * j + 0], base[3 * j + 1],
                                  base[3 * j + 2], 0.f);
            }
            sp[j] = val;
        }
        __syncthreads();

        const int q = qb * WPB + warp;
        if (q >= NPTS) return;

        const float4 qv = sp[q];
        unsigned v = warp_select<32>(sp, NSTEP_G, qv.x, qv.y, qv.z, lane);
        warp_cov_gather_store<32>(sp, v, qv.x, qv.y, qv.z, lane,
                                  g_cov_global + (size_t)(b * NPTS + q) * 6);
    } else {
        // -------- patch 16-NN: 16 queries spanning <= 2 patches --------
        const int pblk = blockIdx.x - GBLKS;
        const int q0 = pblk * WPB;
        const int p0 = q0 / PATCH_P;

        for (int t = threadIdx.x; t < 256; t += 512) {
            const int which = t >> 7;
            const int local = t & 127;
            const int pp = p0 + which;
            float4 val = make_float4(PAD_COORD, PAD_COORD, PAD_COORD, 0.f);
            if (local < PATCH_P && pp < TOTAL_PATCHES) {
                const float* bb = pc + (size_t)pp * PATCH_P * 3;
                val = make_float4(bb[3 * local + 0], bb[3 * local + 1],
                                  bb[3 * local + 2], 0.f);
            }
            sp[(which << 7) + local] = val;
        }
        __syncthreads();

        const int gq = q0 + warp;
        const int pp = gq / PATCH_P;
        const int ql = gq % PATCH_P;
        const float4* spl = sp + ((pp - p0) << 7);

        const float4 qv = spl[ql];
        unsigned v = warp_select<16>(spl, NSTEP_P, qv.x, qv.y, qv.z, lane);
        warp_cov_gather_store<16>(spl, v, qv.x, qv.y, qv.z, lane,
                                  g_cov_patch + (size_t)gq * 6);
    }
}

// ---------------------------------------------------------------------------
// Loss: one eigen per thread (even threads: global, odd: patch), combine via
// shfl with the adjacent lane, mean-reduce.
// ---------------------------------------------------------------------------
__global__ void __launch_bounds__(128)
loss_kernel(float* __restrict__ out)
{
    const int t = blockIdx.x * 128 + threadIdx.x;
    const int i = t >> 1;               // point id
    const int which = t & 1;            // 0 = global, 1 = patch

    float v = 0.0f;
    if (i < TOTAL_PTS) {
        const float* cb = which ? (g_cov_patch  + (size_t)i * 6)
                                : (g_cov_global + (size_t)i * 6);
        float nv[3];
        smallest_evec_abs(cb, nv);
        float ox = __shfl_xor_sync(0xFFFFFFFFu, nv[0], 1);
        float oy = __shfl_xor_sync(0xFFFFFFFFu, nv[1], 1);
        float oz = __shfl_xor_sync(0xFFFFFFFFu, nv[2], 1);
        if (which == 0) {
            float dx = ox - nv[0], dy = oy - nv[1], dz = oz - nv[2];
            v = sqrtf(fmaf(dx, dx, fmaf(dy, dy, dz * dz)));
        }
    }
#pragma unroll
    for (int off = 16; off > 0; off >>= 1)
        v += __shfl_down_sync(0xFFFFFFFFu, v, off);

    __shared__ float warpsum[4];
    const int lane = threadIdx.x & 31;
    const int wid  = threadIdx.x >> 5;
    if (lane == 0) warpsum[wid] = v;
    __syncthreads();

    if (wid == 0) {
        float s = (lane < 4) ? warpsum[lane] : 0.0f;
#pragma unroll
        for (int off = 2; off > 0; off >>= 1)
            s += __shfl_down_sync(0xFFFFFFFFu, s, off);
        if (lane == 0)
            atomicAdd(out, s * (1.0f / (float)TOTAL_PTS));
    }
}

// ---------------------------------------------------------------------------
extern "C" void kernel_launch(void* const* d_in, const int* in_sizes, int n_in,
                              void* d_out, int out_size)
{
    const float* pc = (const float*)d_in[0];
    float* out = (float*)d_out;

    knn_fused_kernel<<<FUSED_BLKS, 512>>>(pc, out);
    loss_kernel<<<(2 * TOTAL_PTS + 127) / 128, 128>>>(out);
}